// round 14
// baseline (speedup 1.0000x reference)
#include <cuda_runtime.h>
#include <cuda_bf16.h>
#include <cstdint>

#define BSZ  2
#define SEQ  192
#define DIN  1024
#define DD   128
#define BS   384            // BSZ*SEQ
#define N2   36864          // SEQ*SEQ
#define N3   7077888        // SEQ^3
#define OUTW 14155776       // BSZ*N3  (one output head)

// -------- scratch (device globals: allocation-free) --------
__device__ float g_P[3 * BS * DD];                           // p, sh, st (fp32)
__device__ unsigned short g_Pbh[3][BS * DD];                 // P bf16 hi [sel][bz][k]
__device__ unsigned short g_Pbl[3][BS * DD];                 // P bf16 lo
__device__ unsigned short g_Yth[3][BSZ * DD * SEQ];          // Y^T hi [sel][b][j][y]
__device__ unsigned short g_Ytl[3][BSZ * DD * SEQ];          // Y^T lo
__device__ unsigned short g_T6h[6][(size_t)BS * DD * DD];    // T hi [head][bz][i][j]
__device__ unsigned short g_T6l[6][(size_t)BS * DD * DD];
__device__ unsigned short g_W6h[6][(size_t)DD * DD * DD];    // W(*) bf16 hi
__device__ unsigned short g_W6l[6][(size_t)DD * DD * DD];    // W(*) bf16 lo

// heads 4,5 use transposed weights W*[a,b,c]=W[b,c,a] so their output is
// natively [b, x, y, z] (the cop permutation). mode: 1=sym-fold, 2=plain
// direct, 3=canonical dual-write (pt_cop sym across CTAs). Z = p for ALL heads.
__constant__ int c_xsel[6] = {1, 1, 1, 2, 0, 0};
__constant__ int c_ysel[6] = {2, 2, 1, 2, 1, 2};
__constant__ int c_mode[6] = {1, 1, 1, 1, 2, 3};

// ======================= helpers =======================
__device__ __forceinline__ uint32_t smem_to_u32(const void* p) {
    uint32_t a;
    asm("{ .reg .u64 t; cvta.to.shared.u64 t, %1; cvt.u32.u64 %0, t; }" : "=r"(a) : "l"(p));
    return a;
}
#define CP_A16(dst, src) \
    asm volatile("cp.async.cg.shared.global [%0], [%1], 16;" :: "r"(dst), "l"(src))
#define CP_COMMIT() asm volatile("cp.async.commit_group;" ::: "memory")
#define CP_WAIT0()  asm volatile("cp.async.wait_group 0;" ::: "memory")
#define CP_WAIT1()  asm volatile("cp.async.wait_group 1;" ::: "memory")

__device__ __forceinline__ void ldsm4(uint32_t* r, uint32_t a) {
    asm volatile("ldmatrix.sync.aligned.m8n8.x4.shared.b16 {%0,%1,%2,%3}, [%4];"
        : "=r"(r[0]), "=r"(r[1]), "=r"(r[2]), "=r"(r[3]) : "r"(a));
}
__device__ __forceinline__ void ldsm4t(uint32_t* r, uint32_t a) {
    asm volatile("ldmatrix.sync.aligned.m8n8.x4.trans.shared.b16 {%0,%1,%2,%3}, [%4];"
        : "=r"(r[0]), "=r"(r[1]), "=r"(r[2]), "=r"(r[3]) : "r"(a));
}
__device__ __forceinline__ void mma16816(float* c, const uint32_t* a, const uint32_t* b) {
    asm volatile("mma.sync.aligned.m16n8k16.row.col.f32.bf16.bf16.f32 "
        "{%0,%1,%2,%3},{%4,%5,%6,%7},{%8,%9},{%0,%1,%2,%3};"
        : "+f"(c[0]), "+f"(c[1]), "+f"(c[2]), "+f"(c[3])
        : "r"(a[0]), "r"(a[1]), "r"(a[2]), "r"(a[3]), "r"(b[0]), "r"(b[1]));
}
__device__ __forceinline__ uint32_t pack_hl(float a, float b, uint32_t& lo_out) {
    __nv_bfloat16 ha = __float2bfloat16(a), hb = __float2bfloat16(b);
    float ra = a - __bfloat162float(ha), rb = b - __bfloat162float(hb);
    __nv_bfloat16 la = __float2bfloat16(ra), lb = __float2bfloat16(rb);
    lo_out = (uint32_t)__bfloat16_as_ushort(la) | ((uint32_t)__bfloat16_as_ushort(lb) << 16);
    return (uint32_t)__bfloat16_as_ushort(ha) | ((uint32_t)__bfloat16_as_ushort(hb) << 16);
}

// warp GEMM, bf16 3-term split (see prior rounds)
template<int MF, int NF2, int NFT, int ARB, int BRB, int KK>
__device__ __forceinline__ void wgemm(uint32_t aH, uint32_t aL,
                                      uint32_t bH, uint32_t bL,
                                      int m0, int n0, int kbase, int lane,
                                      float C[MF][NFT][4])
{
    for (int kk = 0; kk < KK; kk++) {
        uint32_t ah[MF][4], al[MF][4];
        #pragma unroll
        for (int mf = 0; mf < MF; mf++) {
            int r = m0 + mf * 16 + (lane & 15);
            int ck = kbase + kk * 2 + (lane >> 4);
            uint32_t off = (uint32_t)(r * ARB + ((ck ^ (r & 7)) << 4));
            ldsm4(ah[mf], aH + off);
            ldsm4(al[mf], aL + off);
        }
        int rb = kk * 16 + (lane & 15);
        #pragma unroll
        for (int nf2 = 0; nf2 < NF2; nf2++) {
            int ncq = (n0 >> 3) + nf2 * 2 + (lane >> 4);
            uint32_t boff = (uint32_t)(rb * BRB + ((ncq ^ (rb & 7)) << 4));
            uint32_t bh[4], bl[4];
            ldsm4t(bh, bH + boff);
            ldsm4t(bl, bL + boff);
            #pragma unroll
            for (int mf = 0; mf < MF; mf++) {
                mma16816(C[mf][nf2 * 2], ah[mf], bh);
                mma16816(C[mf][nf2 * 2], al[mf], bh);
                mma16816(C[mf][nf2 * 2], ah[mf], bl);
                mma16816(C[mf][nf2 * 2 + 1], ah[mf], bh + 2);
                mma16816(C[mf][nf2 * 2 + 1], al[mf], bh + 2);
                mma16816(C[mf][nf2 * 2 + 1], ah[mf], bl + 2);
            }
        }
    }
}

// =======================================================================
// MLP
// =======================================================================
__global__ void k_mlp(const float* __restrict__ x,
                      const float* __restrict__ W0, const float* __restrict__ b0,
                      const float* __restrict__ W1, const float* __restrict__ b1,
                      const float* __restrict__ W2, const float* __restrict__ b2)
{
    int mat = blockIdx.y;
    const float* W  = (mat == 0) ? W0 : (mat == 1) ? W1 : W2;
    const float* bb = (mat == 0) ? b0 : (mat == 1) ? b1 : b2;
    float* out = g_P + (size_t)mat * BS * DD;
    int row0 = blockIdx.x * 32;
    const float* A = x + (size_t)row0 * DIN;
    __shared__ float xs[32][32];
    __shared__ float ws[32][128];
    int t = threadIdx.x;
    int cx = t & 31, ry = t >> 5;
    float acc[4][4] = {};
    for (int kc = 0; kc < DIN; kc += 32) {
        #pragma unroll
        for (int u = 0; u < 4; u++) {
            int idx = t + u * 256;
            xs[idx >> 5][idx & 31] = A[(idx >> 5) * DIN + kc + (idx & 31)];
        }
        #pragma unroll
        for (int u = 0; u < 16; u++) {
            int idx = t + u * 256;
            ws[idx >> 7][idx & 127] = W[(kc + (idx >> 7)) * DD + (idx & 127)];
        }
        __syncthreads();
        #pragma unroll
        for (int k = 0; k < 32; k++) {
            float4 wv = *(const float4*)&ws[k][cx * 4];
            #pragma unroll
            for (int m = 0; m < 4; m++) {
                float av = xs[ry * 4 + m][k];
                acc[m][0] += av * wv.x; acc[m][1] += av * wv.y;
                acc[m][2] += av * wv.z; acc[m][3] += av * wv.w;
            }
        }
        __syncthreads();
    }
    float4 bv = *(const float4*)&bb[cx * 4];
    #pragma unroll
    for (int m = 0; m < 4; m++) {
        float4 v;
        v.x = acc[m][0] + bv.x; v.y = acc[m][1] + bv.y;
        v.z = acc[m][2] + bv.z; v.w = acc[m][3] + bv.w;
        v.x = v.x > 0.f ? v.x : 0.1f * v.x;
        v.y = v.y > 0.f ? v.y : 0.1f * v.y;
        v.z = v.z > 0.f ? v.z : 0.1f * v.z;
        v.w = v.w > 0.f ? v.w : 0.1f * v.w;
        *(float4*)&out[(size_t)(row0 + ry * 4 + m) * DD + cx * 4] = v;
    }
}

// =======================================================================
// W prep heads 0-3: straight fp32 -> bf16 hi/lo
// =======================================================================
__global__ void k_wprep4(const float* __restrict__ W0, const float* __restrict__ W1,
                         const float* __restrict__ W2, const float* __restrict__ W3)
{
    int head = blockIdx.y;
    const float* W = (head == 0) ? W0 : (head == 1) ? W1 : (head == 2) ? W2 : W3;
    size_t p = (size_t)blockIdx.x * 1024 + threadIdx.x;
    float2 f = *(const float2*)(W + p * 2);
    uint32_t lo;
    uint32_t hi = pack_hl(f.x, f.y, lo);
    ((uint32_t*)g_W6h[head])[p] = hi;
    ((uint32_t*)g_W6l[head])[p] = lo;
}

// =======================================================================
// W prep heads 4,5 (cop): W*[a][b][c] = W[b][c][a]  (16384x128 transpose)
// grid (512 r-tiles, 4 a-tiles, 2), block (32,8)
// =======================================================================
__global__ void k_wprepT(const float* __restrict__ W4, const float* __restrict__ W5)
{
    int head = 4 + blockIdx.z;
    const float* W = blockIdx.z ? W5 : W4;
    int r0 = blockIdx.x * 32, a0 = blockIdx.y * 32;
    __shared__ float t[32][33];
    int tx = threadIdx.x, ty = threadIdx.y;
    #pragma unroll
    for (int ry = 0; ry < 4; ry++)
        t[ty + ry * 8][tx] = W[(size_t)(r0 + ty + ry * 8) * 128 + a0 + tx];
    __syncthreads();
    #pragma unroll
    for (int ry = 0; ry < 4; ry++) {
        int a = a0 + ty + ry * 8, r = r0 + tx;
        float v = t[tx][ty + ry * 8];
        __nv_bfloat16 h = __float2bfloat16(v);
        __nv_bfloat16 l = __float2bfloat16(v - __bfloat162float(h));
        size_t o = (size_t)a * 16384 + r;
        g_W6h[head][o] = __bfloat16_as_ushort(h);
        g_W6l[head][o] = __bfloat16_as_ushort(l);
    }
}

// =======================================================================
// Fused prep: g_P[sel][b][y][j] -> Yt (transposed bf16 hi/lo) AND Pb (packed)
// =======================================================================
__global__ void k_prep()
{
    int sel = blockIdx.z >> 1, b = blockIdx.z & 1;
    int y0 = blockIdx.x * 32, j0 = blockIdx.y * 32;
    const float* src = g_P + (size_t)sel * BS * DD + (size_t)b * SEQ * DD;
    __shared__ float t[32][33];
    int tx = threadIdx.x, ty = threadIdx.y;
    #pragma unroll
    for (int r = 0; r < 4; r++)
        t[ty + r * 8][tx] = src[(size_t)(y0 + ty + r * 8) * DD + j0 + tx];
    __syncthreads();
    #pragma unroll
    for (int r = 0; r < 4; r++) {
        int jj = ty + r * 8, yy = tx;
        float v = t[yy][jj];
        __nv_bfloat16 h = __float2bfloat16(v);
        __nv_bfloat16 l = __float2bfloat16(v - __bfloat162float(h));
        size_t o = (size_t)b * DD * SEQ + (size_t)(j0 + jj) * SEQ + y0 + yy;
        g_Yth[sel][o] = __bfloat16_as_ushort(h);
        g_Ytl[sel][o] = __bfloat16_as_ushort(l);
    }
    #pragma unroll
    for (int r = 0; r < 4; r++) {
        int y = y0 + ty + r * 8, j = j0 + tx;
        float v = t[ty + r * 8][tx];
        __nv_bfloat16 h = __float2bfloat16(v);
        __nv_bfloat16 l = __float2bfloat16(v - __bfloat162float(h));
        size_t o = ((size_t)b * SEQ + y) * DD + j;
        g_Pbh[sel][o] = __bfloat16_as_ushort(h);
        g_Pbl[sel][o] = __bfloat16_as_ushort(l);
    }
}

// =======================================================================
// Stage1, head-batched: T[h][bz,i,j] = sum_k Z[bz,k] W_h[i,k,j]
// Z = p for ALL heads -> one CTA does 2 heads with Z resident in smem.
// grid (128 i, 3 bz-tiles, 3 pairs), 256 threads, 96KB smem
// smem: ZH@0(32K) ZL@32768 ; W chunk (64 krows): WH@65536(16K) WL@81920
// =======================================================================
#define S1_SMEM 98304
__global__ void __launch_bounds__(256, 2) k_stage1_all()
{
    extern __shared__ __align__(16) char smem[];
    uint32_t sb = smem_to_u32(smem);
    int tid = threadIdx.x, lane = tid & 31, w = tid >> 5;
    int i = blockIdx.x, bz0 = blockIdx.y * 128, pair = blockIdx.z;

    // Z (p) full 128 rows x 128 k, hi/lo
    const uint4* Zh4 = (const uint4*)g_Pbh[0] + (size_t)bz0 * 16;
    const uint4* Zl4 = (const uint4*)g_Pbl[0] + (size_t)bz0 * 16;
    for (int idx = tid; idx < 2048; idx += 256) {
        int r = idx >> 4, c = idx & 15;
        uint32_t off = (uint32_t)(r * 256 + ((c ^ (r & 7)) << 4));
        CP_A16(sb + off, Zh4 + idx);
        CP_A16(sb + 32768 + off, Zl4 + idx);
    }
    CP_COMMIT();

    int m0 = (w >> 2) * 64, n0 = (w & 3) * 32;

    for (int hh = 0; hh < 2; hh++) {
        int head = pair * 2 + hh;
        const uint4* Wh4 = (const uint4*)g_W6h[head] + (size_t)i * 2048;
        const uint4* Wl4 = (const uint4*)g_W6l[head] + (size_t)i * 2048;

        float C[4][4][4] = {};
        for (int kc2 = 0; kc2 < 2; kc2++) {
            __syncthreads();                       // W buffer free
            for (int idx = tid; idx < 1024; idx += 256) {   // 64 krows x 16 chunks
                int r = idx >> 4, c = idx & 15;
                uint32_t off = (uint32_t)(r * 256 + ((c ^ (r & 7)) << 4));
                int src = (kc2 * 64 + r) * 16 + c;
                CP_A16(sb + 65536 + off, Wh4 + src);
                CP_A16(sb + 81920 + off, Wl4 + src);
            }
            CP_COMMIT(); CP_WAIT0();               // first wait also covers Z
            __syncthreads();
            wgemm<4, 2, 4, 256, 256, 4>(sb, sb + 32768, sb + 65536, sb + 81920,
                                        m0, n0, kc2 * 8, lane, C);
        }

        uint32_t* TH = (uint32_t*)g_T6h[head];
        uint32_t* TL = (uint32_t*)g_T6l[head];
        #pragma unroll
        for (int mf = 0; mf < 4; mf++)
            #pragma unroll
            for (int nf = 0; nf < 4; nf++) {
                int row = m0 + mf * 16 + (lane >> 2);
                int col = n0 + nf * 8 + (lane & 3) * 2;
                uint32_t lo;
                uint32_t hi = pack_hl(C[mf][nf][0], C[mf][nf][1], lo);
                size_t o = ((size_t)(bz0 + row) * 16384 + (size_t)i * 128 + col) >> 1;
                TH[o] = hi; TL[o] = lo;
                hi = pack_hl(C[mf][nf][2], C[mf][nf][3], lo);
                o = ((size_t)(bz0 + row + 8) * 16384 + (size_t)i * 128 + col) >> 1;
                TH[o] = hi; TL[o] = lo;
            }
    }
}

// =======================================================================
// Fused stage2+3, split-M: grid (2 ti, 384 bz, 6 head), 256 threads
// (unchanged from R12)
// =======================================================================
#define XM_H 0
#define XM_L 24576
#define TB_H 49152
#define TB_L 81920
#define YB0  49152
#define S23_SMEM 114688
__global__ void __launch_bounds__(256, 2) k_stage23_all(float* __restrict__ out)
{
    extern __shared__ __align__(16) char smem[];
    uint32_t sb = smem_to_u32(smem);
    int tid = threadIdx.x, lane = tid & 31, w = tid >> 5;
    int ti = blockIdx.x, bz = blockIdx.y, head = blockIdx.z, b = bz / SEQ;
    int x_ = bz % SEQ;
    int xsel = c_xsel[head], ysel = c_ysel[head], mode = c_mode[head];
    bool narrow = (mode == 1) && (ti == 1);

    if (mode == 3 && ti == 0 && x_ >= 96) return;   // no canonical rows here

    const uint4* Xh4 = (const uint4*)g_Pbh[xsel] + ((size_t)b * SEQ + ti * 96) * 16;
    const uint4* Xl4 = (const uint4*)g_Pbl[xsel] + ((size_t)b * SEQ + ti * 96) * 16;
    const uint4* TH4 = (const uint4*)(g_T6h[head] + (size_t)bz * DD * DD);
    const uint4* TL4 = (const uint4*)(g_T6l[head] + (size_t)bz * DD * DD);
    for (int idx = tid; idx < 1536; idx += 256) {
        int r = idx >> 4, c = idx & 15;
        uint32_t off = (uint32_t)(r * 256 + ((c ^ (r & 7)) << 4));
        CP_A16(sb + XM_H + off, Xh4 + idx);
        CP_A16(sb + XM_L + off, Xl4 + idx);
    }
    for (int idx = tid; idx < 2048; idx += 256) {
        int r = idx >> 4, c = idx & 15;
        uint32_t off = (uint32_t)(r * 256 + ((c ^ (r & 7)) << 4));
        CP_A16(sb + TB_H + off, TH4 + idx);
        CP_A16(sb + TB_L + off, TL4 + idx);
    }
    CP_COMMIT(); CP_WAIT0();
    __syncthreads();

    // ---- stage2: M1 = X @ T ----
    {
        bool s2act = (mode != 3) || (ti * 96 + (w >> 2) * 48 + 48 > x_);
        float C2[3][4][4] = {};
        int m0 = (w >> 2) * 48, n0 = (w & 3) * 32;
        if (s2act)
            wgemm<3, 2, 4, 256, 256, 8>(sb + XM_H, sb + XM_L, sb + TB_H, sb + TB_L,
                                        m0, n0, 0, lane, C2);
        __syncthreads();
        if (s2act) {
            #pragma unroll
            for (int mf = 0; mf < 3; mf++)
                #pragma unroll
                for (int nf = 0; nf < 4; nf++) {
                    int row = m0 + mf * 16 + (lane >> 2);
                    int col = n0 + nf * 8 + (lane & 3) * 2;
                    uint32_t lo0, lo1;
                    uint32_t hi0 = pack_hl(C2[mf][nf][0], C2[mf][nf][1], lo0);
                    uint32_t hi1 = pack_hl(C2[mf][nf][2], C2[mf][nf][3], lo1);
                    int r2 = row + 8;
                    uint32_t o0 = (uint32_t)(row * 256 + (((col >> 3) ^ (row & 7)) << 4) + (col & 7) * 2);
                    uint32_t o1 = (uint32_t)(r2 * 256 + (((col >> 3) ^ (r2 & 7)) << 4) + (col & 7) * 2);
                    *(uint32_t*)(smem + XM_H + o0) = hi0;
                    *(uint32_t*)(smem + XM_L + o0) = lo0;
                    *(uint32_t*)(smem + XM_H + o1) = hi1;
                    *(uint32_t*)(smem + XM_L + o1) = lo1;
                }
        }
    }
    __syncthreads();

    // ---- stage3: S = M1 @ Y^T, 4 pipelined 32-j-row chunks ----
    int m3, n3, nfmax; bool act;
    if (narrow)      { act = (w < 6); m3 = (w / 3) * 48; n3 = 96 + (w % 3) * 32; nfmax = 4; }
    else             { m3 = (w >> 2) * 48; n3 = (w & 3) * 48; nfmax = 6;
                       act = (mode != 3) || (ti * 96 + m3 + 48 > x_); }

    const uint4* YH4 = (const uint4*)(g_Yth[ysel] + (size_t)b * DD * SEQ);
    const uint4* YL4 = (const uint4*)(g_Ytl[ysel] + (size_t)b * DD * SEQ);
    auto loadY = [&](int jc) {
        uint32_t base = sb + YB0 + (uint32_t)(jc & 1) * 24576;
        for (int idx = tid; idx < 768; idx += 256) {
            int r = idx / 24, c = idx % 24;
            uint32_t off = (uint32_t)(r * 384 + ((c ^ (r & 7)) << 4));
            int src = (jc * 32 + r) * 24 + c;
            CP_A16(base + off, YH4 + src);
            CP_A16(base + 12288 + off, YL4 + src);
        }
        CP_COMMIT();
    };

    float C3[3][6][4] = {};
    loadY(0);
    for (int jc = 0; jc < 4; jc++) {
        if (jc < 3) { loadY(jc + 1); CP_WAIT1(); } else CP_WAIT0();
        __syncthreads();
        uint32_t yb = sb + YB0 + (uint32_t)(jc & 1) * 24576;
        if (act) {
            if (!narrow)
                wgemm<3, 3, 6, 256, 384, 2>(sb + XM_H, sb + XM_L, yb, yb + 12288,
                                            m3, n3, jc * 4, lane, C3);
            else
                wgemm<3, 2, 6, 256, 384, 2>(sb + XM_H, sb + XM_L, yb, yb + 12288,
                                            m3, n3, jc * 4, lane, C3);
        }
        __syncthreads();
    }

    // ---- epilogue ----
    float* Ssm = (float*)smem;
    if (act) {
        #pragma unroll
        for (int mf = 0; mf < 3; mf++)
            for (int nf = 0; nf < nfmax; nf++) {
                int row = m3 + mf * 16 + (lane >> 2);
                int col = n3 + nf * 8 + (lane & 3) * 2;
                Ssm[row * 193 + col]           = C3[mf][nf][0];
                Ssm[row * 193 + col + 1]       = C3[mf][nf][1];
                Ssm[(row + 8) * 193 + col]     = C3[mf][nf][2];
                Ssm[(row + 8) * 193 + col + 1] = C3[mf][nf][3];
            }
    }
    __syncthreads();

    float* dsth = out + (size_t)head * OUTW;

    if (mode == 2) {
        float* dst = dsth + (size_t)bz * N2;
        for (int idx = tid * 4; idx < 96 * SEQ; idx += 1024) {
            int r = idx / SEQ, y = idx % SEQ;
            float4 v = make_float4(Ssm[r * 193 + y],     Ssm[r * 193 + y + 1],
                                   Ssm[r * 193 + y + 2], Ssm[r * 193 + y + 3]);
            *(float4*)(dst + (size_t)(ti * 96 + r) * SEQ + y) = v;
        }
    } else if (mode == 3) {
        for (int idx = tid * 4; idx < 96 * SEQ; idx += 1024) {
            int r = idx / SEQ, zc = idx % SEQ;
            int y = ti * 96 + r;
            if (y < x_) continue;
            float4 v = make_float4(Ssm[r * 193 + zc],     Ssm[r * 193 + zc + 1],
                                   Ssm[r * 193 + zc + 2], Ssm[r * 193 + zc + 3]);
            *(float4*)(dsth + ((size_t)bz * SEQ + y) * SEQ + zc) = v;
            *(float4*)(dsth + (((size_t)b * SEQ + y) * SEQ + x_) * SEQ + zc) = v;
        }
    } else if (ti == 0) {
        float* dst = dsth + (size_t)bz * N2;
        for (int idx = tid * 4; idx < 96 * SEQ; idx += 1024) {
            int r = idx / SEQ, y = idx % SEQ;
            float4 v;
            v.x = (r <= y)     ? Ssm[r * 193 + y]     : Ssm[y * 193 + r];
            v.y = (r <= y + 1) ? Ssm[r * 193 + y + 1] : Ssm[(y + 1) * 193 + r];
            v.z = (r <= y + 2) ? Ssm[r * 193 + y + 2] : Ssm[(y + 2) * 193 + r];
            v.w = (r <= y + 3) ? Ssm[r * 193 + y + 3] : Ssm[(y + 3) * 193 + r];
            *(float4*)(dst + (size_t)r * SEQ + y) = v;
        }
        for (int idx = tid * 4; idx < 96 * 96; idx += 1024) {
            int r2 = idx / 96, c2 = idx % 96;
            float4 v = make_float4(Ssm[c2 * 193 + 96 + r2],
                                   Ssm[(c2 + 1) * 193 + 96 + r2],
                                   Ssm[(c2 + 2) * 193 + 96 + r2],
                                   Ssm[(c2 + 3) * 193 + 96 + r2]);
            *(float4*)(dst + (size_t)(96 + r2) * SEQ + c2) = v;
        }
    } else {
        float* dst = dsth + (size_t)bz * N2;
        for (int idx = tid * 4; idx < 96 * 96; idx += 1024) {
            int r = idx / 96, c = idx % 96;
            float4 v;
            v.x = (r <= c)     ? Ssm[r * 193 + 96 + c]     : Ssm[c * 193 + 96 + r];
            v.y = (r <= c + 1) ? Ssm[r * 193 + 96 + c + 1] : Ssm[(c + 1) * 193 + 96 + r];
            v.z = (r <= c + 2) ? Ssm[r * 193 + 96 + c + 2] : Ssm[(c + 2) * 193 + 96 + r];
            v.w = (r <= c + 3) ? Ssm[r * 193 + 96 + c + 3] : Ssm[(c + 3) * 193 + 96 + r];
            *(float4*)(dst + (size_t)(96 + r) * SEQ + 96 + c) = v;
        }
    }
}

// =======================================================================
extern "C" void kernel_launch(void* const* d_in, const int* in_sizes, int n_in,
                              void* d_out, int out_size)
{
    const float* x  = (const float*)d_in[0];
    const float* Wp = (const float*)d_in[1];
    const float* bp = (const float*)d_in[2];
    const float* Wh = (const float*)d_in[3];
    const float* bh = (const float*)d_in[4];
    const float* Wt = (const float*)d_in[5];
    const float* bt = (const float*)d_in[6];
    float* out = (float*)d_out;

    cudaFuncSetAttribute(k_stage1_all,  cudaFuncAttributeMaxDynamicSharedMemorySize, S1_SMEM);
    cudaFuncSetAttribute(k_stage23_all, cudaFuncAttributeMaxDynamicSharedMemorySize, S23_SMEM);

    k_wprep4<<<dim3(1024, 4), 1024>>>(
        (const float*)d_in[7], (const float*)d_in[8],
        (const float*)d_in[9], (const float*)d_in[10]);
    k_wprepT<<<dim3(512, 4, 2), dim3(32, 8)>>>(
        (const float*)d_in[11], (const float*)d_in[12]);
    k_mlp<<<dim3(12, 3), 256>>>(x, Wp, bp, Wh, bh, Wt, bt);
    k_prep<<<dim3(6, 4, 6), dim3(32, 8)>>>();
    k_stage1_all<<<dim3(128, 3, 3), 256, S1_SMEM>>>();
    k_stage23_all<<<dim3(2, 384, 6), 256, S23_SMEM>>>(out);
}

// round 15
// speedup vs baseline: 1.0487x; 1.0487x over previous
#include <cuda_runtime.h>
#include <cuda_bf16.h>
#include <cstdint>

#define BSZ  2
#define SEQ  192
#define DIN  1024
#define DD   128
#define BS   384            // BSZ*SEQ
#define N2   36864          // SEQ*SEQ
#define N3   7077888        // SEQ^3
#define OUTW 14155776       // BSZ*N3  (one output head)

// -------- scratch (device globals: allocation-free) --------
__device__ float g_P[3 * BS * DD];                           // p, sh, st (fp32)
__device__ unsigned short g_Pbh[3][BS * DD];                 // P bf16 hi [sel][bz][k]
__device__ unsigned short g_Pbl[3][BS * DD];                 // P bf16 lo
__device__ unsigned short g_Yth[3][BSZ * DD * SEQ];          // Y^T hi [sel][b][j][y]
__device__ unsigned short g_Ytl[3][BSZ * DD * SEQ];          // Y^T lo
__device__ unsigned short g_T6h[6][(size_t)BS * DD * DD];    // T hi [head][bz][i][j]
__device__ unsigned short g_T6l[6][(size_t)BS * DD * DD];
__device__ unsigned short g_W6h[6][(size_t)DD * DD * DD];    // W(*) bf16 hi
__device__ unsigned short g_W6l[6][(size_t)DD * DD * DD];    // W(*) bf16 lo

// heads 4,5 use transposed weights W*[a,b,c]=W[b,c,a] so their output is
// natively [b, x, y, z] (the cop permutation). mode: 1=sym-fold, 2=plain
// direct, 3=canonical dual-write (pt_cop sym across CTAs). Z = p for ALL heads.
__constant__ int c_xsel[6] = {1, 1, 1, 2, 0, 0};
__constant__ int c_zsel[6] = {0, 0, 0, 0, 0, 0};
__constant__ int c_ysel[6] = {2, 2, 1, 2, 1, 2};
__constant__ int c_mode[6] = {1, 1, 1, 1, 2, 3};

// ======================= helpers =======================
__device__ __forceinline__ uint32_t smem_to_u32(const void* p) {
    uint32_t a;
    asm("{ .reg .u64 t; cvta.to.shared.u64 t, %1; cvt.u32.u64 %0, t; }" : "=r"(a) : "l"(p));
    return a;
}
#define CP_A16(dst, src) \
    asm volatile("cp.async.cg.shared.global [%0], [%1], 16;" :: "r"(dst), "l"(src))
#define CP_COMMIT() asm volatile("cp.async.commit_group;" ::: "memory")
#define CP_WAIT0()  asm volatile("cp.async.wait_group 0;" ::: "memory")
#define CP_WAIT1()  asm volatile("cp.async.wait_group 1;" ::: "memory")

__device__ __forceinline__ void ldsm4(uint32_t* r, uint32_t a) {
    asm volatile("ldmatrix.sync.aligned.m8n8.x4.shared.b16 {%0,%1,%2,%3}, [%4];"
        : "=r"(r[0]), "=r"(r[1]), "=r"(r[2]), "=r"(r[3]) : "r"(a));
}
__device__ __forceinline__ void ldsm4t(uint32_t* r, uint32_t a) {
    asm volatile("ldmatrix.sync.aligned.m8n8.x4.trans.shared.b16 {%0,%1,%2,%3}, [%4];"
        : "=r"(r[0]), "=r"(r[1]), "=r"(r[2]), "=r"(r[3]) : "r"(a));
}
__device__ __forceinline__ void mma16816(float* c, const uint32_t* a, const uint32_t* b) {
    asm volatile("mma.sync.aligned.m16n8k16.row.col.f32.bf16.bf16.f32 "
        "{%0,%1,%2,%3},{%4,%5,%6,%7},{%8,%9},{%0,%1,%2,%3};"
        : "+f"(c[0]), "+f"(c[1]), "+f"(c[2]), "+f"(c[3])
        : "r"(a[0]), "r"(a[1]), "r"(a[2]), "r"(a[3]), "r"(b[0]), "r"(b[1]));
}
__device__ __forceinline__ uint32_t pack_hl(float a, float b, uint32_t& lo_out) {
    __nv_bfloat16 ha = __float2bfloat16(a), hb = __float2bfloat16(b);
    float ra = a - __bfloat162float(ha), rb = b - __bfloat162float(hb);
    __nv_bfloat16 la = __float2bfloat16(ra), lb = __float2bfloat16(rb);
    lo_out = (uint32_t)__bfloat16_as_ushort(la) | ((uint32_t)__bfloat16_as_ushort(lb) << 16);
    return (uint32_t)__bfloat16_as_ushort(ha) | ((uint32_t)__bfloat16_as_ushort(hb) << 16);
}

// warp GEMM, bf16 3-term split (see prior rounds)
template<int MF, int NF2, int NFT, int ARB, int BRB, int KK>
__device__ __forceinline__ void wgemm(uint32_t aH, uint32_t aL,
                                      uint32_t bH, uint32_t bL,
                                      int m0, int n0, int kbase, int lane,
                                      float C[MF][NFT][4])
{
    for (int kk = 0; kk < KK; kk++) {
        uint32_t ah[MF][4], al[MF][4];
        #pragma unroll
        for (int mf = 0; mf < MF; mf++) {
            int r = m0 + mf * 16 + (lane & 15);
            int ck = kbase + kk * 2 + (lane >> 4);
            uint32_t off = (uint32_t)(r * ARB + ((ck ^ (r & 7)) << 4));
            ldsm4(ah[mf], aH + off);
            ldsm4(al[mf], aL + off);
        }
        int rb = kk * 16 + (lane & 15);
        #pragma unroll
        for (int nf2 = 0; nf2 < NF2; nf2++) {
            int ncq = (n0 >> 3) + nf2 * 2 + (lane >> 4);
            uint32_t boff = (uint32_t)(rb * BRB + ((ncq ^ (rb & 7)) << 4));
            uint32_t bh[4], bl[4];
            ldsm4t(bh, bH + boff);
            ldsm4t(bl, bL + boff);
            #pragma unroll
            for (int mf = 0; mf < MF; mf++) {
                mma16816(C[mf][nf2 * 2], ah[mf], bh);
                mma16816(C[mf][nf2 * 2], al[mf], bh);
                mma16816(C[mf][nf2 * 2], ah[mf], bl);
                mma16816(C[mf][nf2 * 2 + 1], ah[mf], bh + 2);
                mma16816(C[mf][nf2 * 2 + 1], al[mf], bh + 2);
                mma16816(C[mf][nf2 * 2 + 1], ah[mf], bl + 2);
            }
        }
    }
}

// =======================================================================
// MLP
// =======================================================================
__global__ void k_mlp(const float* __restrict__ x,
                      const float* __restrict__ W0, const float* __restrict__ b0,
                      const float* __restrict__ W1, const float* __restrict__ b1,
                      const float* __restrict__ W2, const float* __restrict__ b2)
{
    int mat = blockIdx.y;
    const float* W  = (mat == 0) ? W0 : (mat == 1) ? W1 : W2;
    const float* bb = (mat == 0) ? b0 : (mat == 1) ? b1 : b2;
    float* out = g_P + (size_t)mat * BS * DD;
    int row0 = blockIdx.x * 32;
    const float* A = x + (size_t)row0 * DIN;
    __shared__ float xs[32][32];
    __shared__ float ws[32][128];
    int t = threadIdx.x;
    int cx = t & 31, ry = t >> 5;
    float acc[4][4] = {};
    for (int kc = 0; kc < DIN; kc += 32) {
        #pragma unroll
        for (int u = 0; u < 4; u++) {
            int idx = t + u * 256;
            xs[idx >> 5][idx & 31] = A[(idx >> 5) * DIN + kc + (idx & 31)];
        }
        #pragma unroll
        for (int u = 0; u < 16; u++) {
            int idx = t + u * 256;
            ws[idx >> 7][idx & 127] = W[(kc + (idx >> 7)) * DD + (idx & 127)];
        }
        __syncthreads();
        #pragma unroll
        for (int k = 0; k < 32; k++) {
            float4 wv = *(const float4*)&ws[k][cx * 4];
            #pragma unroll
            for (int m = 0; m < 4; m++) {
                float av = xs[ry * 4 + m][k];
                acc[m][0] += av * wv.x; acc[m][1] += av * wv.y;
                acc[m][2] += av * wv.z; acc[m][3] += av * wv.w;
            }
        }
        __syncthreads();
    }
    float4 bv = *(const float4*)&bb[cx * 4];
    #pragma unroll
    for (int m = 0; m < 4; m++) {
        float4 v;
        v.x = acc[m][0] + bv.x; v.y = acc[m][1] + bv.y;
        v.z = acc[m][2] + bv.z; v.w = acc[m][3] + bv.w;
        v.x = v.x > 0.f ? v.x : 0.1f * v.x;
        v.y = v.y > 0.f ? v.y : 0.1f * v.y;
        v.z = v.z > 0.f ? v.z : 0.1f * v.z;
        v.w = v.w > 0.f ? v.w : 0.1f * v.w;
        *(float4*)&out[(size_t)(row0 + ry * 4 + m) * DD + cx * 4] = v;
    }
}

// =======================================================================
// W prep heads 0-3: straight fp32 -> bf16 hi/lo
// =======================================================================
__global__ void k_wprep4(const float* __restrict__ W0, const float* __restrict__ W1,
                         const float* __restrict__ W2, const float* __restrict__ W3)
{
    int head = blockIdx.y;
    const float* W = (head == 0) ? W0 : (head == 1) ? W1 : (head == 2) ? W2 : W3;
    size_t p = (size_t)blockIdx.x * 1024 + threadIdx.x;
    float2 f = *(const float2*)(W + p * 2);
    uint32_t lo;
    uint32_t hi = pack_hl(f.x, f.y, lo);
    ((uint32_t*)g_W6h[head])[p] = hi;
    ((uint32_t*)g_W6l[head])[p] = lo;
}

// =======================================================================
// W prep heads 4,5 (cop): W*[a][b][c] = W[b][c][a]  (16384x128 transpose)
// grid (512 r-tiles, 4 a-tiles, 2), block (32,8)
// =======================================================================
__global__ void k_wprepT(const float* __restrict__ W4, const float* __restrict__ W5)
{
    int head = 4 + blockIdx.z;
    const float* W = blockIdx.z ? W5 : W4;
    int r0 = blockIdx.x * 32, a0 = blockIdx.y * 32;
    __shared__ float t[32][33];
    int tx = threadIdx.x, ty = threadIdx.y;
    #pragma unroll
    for (int ry = 0; ry < 4; ry++)
        t[ty + ry * 8][tx] = W[(size_t)(r0 + ty + ry * 8) * 128 + a0 + tx];
    __syncthreads();
    #pragma unroll
    for (int ry = 0; ry < 4; ry++) {
        int a = a0 + ty + ry * 8, r = r0 + tx;
        float v = t[tx][ty + ry * 8];
        __nv_bfloat16 h = __float2bfloat16(v);
        __nv_bfloat16 l = __float2bfloat16(v - __bfloat162float(h));
        size_t o = (size_t)a * 16384 + r;
        g_W6h[head][o] = __bfloat16_as_ushort(h);
        g_W6l[head][o] = __bfloat16_as_ushort(l);
    }
}

// =======================================================================
// Fused prep: g_P[sel][b][y][j] -> Yt (transposed bf16 hi/lo) AND Pb (packed)
// =======================================================================
__global__ void k_prep()
{
    int sel = blockIdx.z >> 1, b = blockIdx.z & 1;
    int y0 = blockIdx.x * 32, j0 = blockIdx.y * 32;
    const float* src = g_P + (size_t)sel * BS * DD + (size_t)b * SEQ * DD;
    __shared__ float t[32][33];
    int tx = threadIdx.x, ty = threadIdx.y;
    #pragma unroll
    for (int r = 0; r < 4; r++)
        t[ty + r * 8][tx] = src[(size_t)(y0 + ty + r * 8) * DD + j0 + tx];
    __syncthreads();
    #pragma unroll
    for (int r = 0; r < 4; r++) {
        int jj = ty + r * 8, yy = tx;
        float v = t[yy][jj];
        __nv_bfloat16 h = __float2bfloat16(v);
        __nv_bfloat16 l = __float2bfloat16(v - __bfloat162float(h));
        size_t o = (size_t)b * DD * SEQ + (size_t)(j0 + jj) * SEQ + y0 + yy;
        g_Yth[sel][o] = __bfloat16_as_ushort(h);
        g_Ytl[sel][o] = __bfloat16_as_ushort(l);
    }
    #pragma unroll
    for (int r = 0; r < 4; r++) {
        int y = y0 + ty + r * 8, j = j0 + tx;
        float v = t[ty + r * 8][tx];
        __nv_bfloat16 h = __float2bfloat16(v);
        __nv_bfloat16 l = __float2bfloat16(v - __bfloat162float(h));
        size_t o = ((size_t)b * SEQ + y) * DD + j;
        g_Pbh[sel][o] = __bfloat16_as_ushort(h);
        g_Pbl[sel][o] = __bfloat16_as_ushort(l);
    }
}

// =======================================================================
// Stage1: T[h][bz,i,j] = sum_k Z[bz,k] Wh[i,k,j]  (Wh = W or W*)  [R12 form]
// grid (128 i, 3 bz-tiles, 6 heads), 256 threads, 64KB smem, K-chunked
// =======================================================================
#define S1_SMEM 65536
__global__ void __launch_bounds__(256, 2) k_stage1_all()
{
    extern __shared__ __align__(16) char smem[];
    uint32_t sb = smem_to_u32(smem);
    int tid = threadIdx.x, lane = tid & 31, w = tid >> 5;
    int i = blockIdx.x, bz0 = blockIdx.y * 128, head = blockIdx.z;
    int zsel = c_zsel[head];
    const uint4* Zh4 = (const uint4*)g_Pbh[zsel] + (size_t)bz0 * 16;
    const uint4* Zl4 = (const uint4*)g_Pbl[zsel] + (size_t)bz0 * 16;
    const uint4* Wh4 = (const uint4*)g_W6h[head] + (size_t)i * 2048;
    const uint4* Wl4 = (const uint4*)g_W6l[head] + (size_t)i * 2048;

    float C[4][4][4] = {};
    int m0 = (w >> 2) * 64, n0 = (w & 3) * 32;

    for (int kc = 0; kc < 128; kc += 64) {
        __syncthreads();
        for (int idx = tid; idx < 1024; idx += 256) {
            int r = idx >> 3, c = idx & 7;
            uint32_t off = (uint32_t)(r * 128 + ((c ^ (r & 7)) << 4));
            int src = r * 16 + (kc >> 3) + c;
            CP_A16(sb + off, Zh4 + src);
            CP_A16(sb + 16384 + off, Zl4 + src);
        }
        for (int idx = tid; idx < 1024; idx += 256) {
            int r = idx >> 4, c = idx & 15;
            uint32_t off = (uint32_t)(r * 256 + ((c ^ (r & 7)) << 4));
            int src = (kc + r) * 16 + c;
            CP_A16(sb + 32768 + off, Wh4 + src);
            CP_A16(sb + 49152 + off, Wl4 + src);
        }
        CP_COMMIT(); CP_WAIT0();
        __syncthreads();
        wgemm<4, 2, 4, 128, 256, 4>(sb, sb + 16384, sb + 32768, sb + 49152,
                                    m0, n0, 0, lane, C);
    }

    uint32_t* TH = (uint32_t*)g_T6h[head];
    uint32_t* TL = (uint32_t*)g_T6l[head];
    #pragma unroll
    for (int mf = 0; mf < 4; mf++)
        #pragma unroll
        for (int nf = 0; nf < 4; nf++) {
            int row = m0 + mf * 16 + (lane >> 2);
            int col = n0 + nf * 8 + (lane & 3) * 2;
            uint32_t lo;
            uint32_t hi = pack_hl(C[mf][nf][0], C[mf][nf][1], lo);
            size_t o = ((size_t)(bz0 + row) * 16384 + (size_t)i * 128 + col) >> 1;
            TH[o] = hi; TL[o] = lo;
            hi = pack_hl(C[mf][nf][2], C[mf][nf][3], lo);
            o = ((size_t)(bz0 + row + 8) * 16384 + (size_t)i * 128 + col) >> 1;
            TH[o] = hi; TL[o] = lo;
        }
}

// =======================================================================
// Fused stage2+3, split-M: grid (2 ti, 384 bz, 6 head), 256 threads [R12]
// mode 1: sym fold in-CTA; mode 2: plain direct; mode 3: canonical dual.
// NEW: mode-1 ti=0 skips warp tile (rows 48-95, cols 0-47) in stage3 —
// that Ssm region is provably never read by the folded epilogue.
// =======================================================================
#define XM_H 0
#define XM_L 24576
#define TB_H 49152
#define TB_L 81920
#define YB0  49152
#define S23_SMEM 114688
__global__ void __launch_bounds__(256, 2) k_stage23_all(float* __restrict__ out)
{
    extern __shared__ __align__(16) char smem[];
    uint32_t sb = smem_to_u32(smem);
    int tid = threadIdx.x, lane = tid & 31, w = tid >> 5;
    int ti = blockIdx.x, bz = blockIdx.y, head = blockIdx.z, b = bz / SEQ;
    int x_ = bz % SEQ;
    int xsel = c_xsel[head], ysel = c_ysel[head], mode = c_mode[head];
    bool narrow = (mode == 1) && (ti == 1);

    if (mode == 3 && ti == 0 && x_ >= 96) return;   // no canonical rows here

    const uint4* Xh4 = (const uint4*)g_Pbh[xsel] + ((size_t)b * SEQ + ti * 96) * 16;
    const uint4* Xl4 = (const uint4*)g_Pbl[xsel] + ((size_t)b * SEQ + ti * 96) * 16;
    const uint4* TH4 = (const uint4*)(g_T6h[head] + (size_t)bz * DD * DD);
    const uint4* TL4 = (const uint4*)(g_T6l[head] + (size_t)bz * DD * DD);
    for (int idx = tid; idx < 1536; idx += 256) {
        int r = idx >> 4, c = idx & 15;
        uint32_t off = (uint32_t)(r * 256 + ((c ^ (r & 7)) << 4));
        CP_A16(sb + XM_H + off, Xh4 + idx);
        CP_A16(sb + XM_L + off, Xl4 + idx);
    }
    for (int idx = tid; idx < 2048; idx += 256) {
        int r = idx >> 4, c = idx & 15;
        uint32_t off = (uint32_t)(r * 256 + ((c ^ (r & 7)) << 4));
        CP_A16(sb + TB_H + off, TH4 + idx);
        CP_A16(sb + TB_L + off, TL4 + idx);
    }
    CP_COMMIT(); CP_WAIT0();
    __syncthreads();

    // ---- stage2: M1 = X @ T ----
    {
        bool s2act = (mode != 3) || (ti * 96 + (w >> 2) * 48 + 48 > x_);
        float C2[3][4][4] = {};
        int m0 = (w >> 2) * 48, n0 = (w & 3) * 32;
        if (s2act)
            wgemm<3, 2, 4, 256, 256, 8>(sb + XM_H, sb + XM_L, sb + TB_H, sb + TB_L,
                                        m0, n0, 0, lane, C2);
        __syncthreads();
        if (s2act) {
            #pragma unroll
            for (int mf = 0; mf < 3; mf++)
                #pragma unroll
                for (int nf = 0; nf < 4; nf++) {
                    int row = m0 + mf * 16 + (lane >> 2);
                    int col = n0 + nf * 8 + (lane & 3) * 2;
                    uint32_t lo0, lo1;
                    uint32_t hi0 = pack_hl(C2[mf][nf][0], C2[mf][nf][1], lo0);
                    uint32_t hi1 = pack_hl(C2[mf][nf][2], C2[mf][nf][3], lo1);
                    int r2 = row + 8;
                    uint32_t o0 = (uint32_t)(row * 256 + (((col >> 3) ^ (row & 7)) << 4) + (col & 7) * 2);
                    uint32_t o1 = (uint32_t)(r2 * 256 + (((col >> 3) ^ (r2 & 7)) << 4) + (col & 7) * 2);
                    *(uint32_t*)(smem + XM_H + o0) = hi0;
                    *(uint32_t*)(smem + XM_L + o0) = lo0;
                    *(uint32_t*)(smem + XM_H + o1) = hi1;
                    *(uint32_t*)(smem + XM_L + o1) = lo1;
                }
        }
    }
    __syncthreads();

    // ---- stage3: S = M1 @ Y^T, 4 pipelined 32-j-row chunks ----
    int m3, n3, nfmax; bool act;
    if (narrow)      { act = (w < 6); m3 = (w / 3) * 48; n3 = 96 + (w % 3) * 32; nfmax = 4; }
    else             { m3 = (w >> 2) * 48; n3 = (w & 3) * 48; nfmax = 6;
                       act = ((mode != 3) || (ti * 96 + m3 + 48 > x_))
                             && !(mode == 1 && ti == 0 && m3 == 48 && n3 == 0); }

    const uint4* YH4 = (const uint4*)(g_Yth[ysel] + (size_t)b * DD * SEQ);
    const uint4* YL4 = (const uint4*)(g_Ytl[ysel] + (size_t)b * DD * SEQ);
    auto loadY = [&](int jc) {
        uint32_t base = sb + YB0 + (uint32_t)(jc & 1) * 24576;
        for (int idx = tid; idx < 768; idx += 256) {
            int r = idx / 24, c = idx % 24;
            uint32_t off = (uint32_t)(r * 384 + ((c ^ (r & 7)) << 4));
            int src = (jc * 32 + r) * 24 + c;
            CP_A16(base + off, YH4 + src);
            CP_A16(base + 12288 + off, YL4 + src);
        }
        CP_COMMIT();
    };

    float C3[3][6][4] = {};
    loadY(0);
    for (int jc = 0; jc < 4; jc++) {
        if (jc < 3) { loadY(jc + 1); CP_WAIT1(); } else CP_WAIT0();
        __syncthreads();
        uint32_t yb = sb + YB0 + (uint32_t)(jc & 1) * 24576;
        if (act) {
            if (!narrow)
                wgemm<3, 3, 6, 256, 384, 2>(sb + XM_H, sb + XM_L, yb, yb + 12288,
                                            m3, n3, jc * 4, lane, C3);
            else
                wgemm<3, 2, 6, 256, 384, 2>(sb + XM_H, sb + XM_L, yb, yb + 12288,
                                            m3, n3, jc * 4, lane, C3);
        }
        __syncthreads();
    }

    // ---- epilogue ----
    float* Ssm = (float*)smem;
    if (act) {
        #pragma unroll
        for (int mf = 0; mf < 3; mf++)
            for (int nf = 0; nf < nfmax; nf++) {
                int row = m3 + mf * 16 + (lane >> 2);
                int col = n3 + nf * 8 + (lane & 3) * 2;
                Ssm[row * 193 + col]           = C3[mf][nf][0];
                Ssm[row * 193 + col + 1]       = C3[mf][nf][1];
                Ssm[(row + 8) * 193 + col]     = C3[mf][nf][2];
                Ssm[(row + 8) * 193 + col + 1] = C3[mf][nf][3];
            }
    }
    __syncthreads();

    float* dsth = out + (size_t)head * OUTW;

    if (mode == 2) {
        float* dst = dsth + (size_t)bz * N2;
        for (int idx = tid * 4; idx < 96 * SEQ; idx += 1024) {
            int r = idx / SEQ, y = idx % SEQ;
            float4 v = make_float4(Ssm[r * 193 + y],     Ssm[r * 193 + y + 1],
                                   Ssm[r * 193 + y + 2], Ssm[r * 193 + y + 3]);
            *(float4*)(dst + (size_t)(ti * 96 + r) * SEQ + y) = v;
        }
    } else if (mode == 3) {
        for (int idx = tid * 4; idx < 96 * SEQ; idx += 1024) {
            int r = idx / SEQ, zc = idx % SEQ;
            int y = ti * 96 + r;
            if (y < x_) continue;
            float4 v = make_float4(Ssm[r * 193 + zc],     Ssm[r * 193 + zc + 1],
                                   Ssm[r * 193 + zc + 2], Ssm[r * 193 + zc + 3]);
            *(float4*)(dsth + ((size_t)bz * SEQ + y) * SEQ + zc) = v;
            *(float4*)(dsth + (((size_t)b * SEQ + y) * SEQ + x_) * SEQ + zc) = v;
        }
    } else if (ti == 0) {
        float* dst = dsth + (size_t)bz * N2;
        for (int idx = tid * 4; idx < 96 * SEQ; idx += 1024) {
            int r = idx / SEQ, y = idx % SEQ;
            float4 v;
            v.x = (r <= y)     ? Ssm[r * 193 + y]     : Ssm[y * 193 + r];
            v.y = (r <= y + 1) ? Ssm[r * 193 + y + 1] : Ssm[(y + 1) * 193 + r];
            v.z = (r <= y + 2) ? Ssm[r * 193 + y + 2] : Ssm[(y + 2) * 193 + r];
            v.w = (r <= y + 3) ? Ssm[r * 193 + y + 3] : Ssm[(y + 3) * 193 + r];
            *(float4*)(dst + (size_t)r * SEQ + y) = v;
        }
        for (int idx = tid * 4; idx < 96 * 96; idx += 1024) {
            int r2 = idx / 96, c2 = idx % 96;
            float4 v = make_float4(Ssm[c2 * 193 + 96 + r2],
                                   Ssm[(c2 + 1) * 193 + 96 + r2],
                                   Ssm[(c2 + 2) * 193 + 96 + r2],
                                   Ssm[(c2 + 3) * 193 + 96 + r2]);
            *(float4*)(dst + (size_t)(96 + r2) * SEQ + c2) = v;
        }
    } else {
        float* dst = dsth + (size_t)bz * N2;
        for (int idx = tid * 4; idx < 96 * 96; idx += 1024) {
            int r = idx / 96, c = idx % 96;
            float4 v;
            v.x = (r <= c)     ? Ssm[r * 193 + 96 + c]     : Ssm[c * 193 + 96 + r];
            v.y = (r <= c + 1) ? Ssm[r * 193 + 96 + c + 1] : Ssm[(c + 1) * 193 + 96 + r];
            v.z = (r <= c + 2) ? Ssm[r * 193 + 96 + c + 2] : Ssm[(c + 2) * 193 + 96 + r];
            v.w = (r <= c + 3) ? Ssm[r * 193 + 96 + c + 3] : Ssm[(c + 3) * 193 + 96 + r];
            *(float4*)(dst + (size_t)(96 + r) * SEQ + 96 + c) = v;
        }
    }
}

// =======================================================================
extern "C" void kernel_launch(void* const* d_in, const int* in_sizes, int n_in,
                              void* d_out, int out_size)
{
    const float* x  = (const float*)d_in[0];
    const float* Wp = (const float*)d_in[1];
    const float* bp = (const float*)d_in[2];
    const float* Wh = (const float*)d_in[3];
    const float* bh = (const float*)d_in[4];
    const float* Wt = (const float*)d_in[5];
    const float* bt = (const float*)d_in[6];
    float* out = (float*)d_out;

    cudaFuncSetAttribute(k_stage1_all,  cudaFuncAttributeMaxDynamicSharedMemorySize, S1_SMEM);
    cudaFuncSetAttribute(k_stage23_all, cudaFuncAttributeMaxDynamicSharedMemorySize, S23_SMEM);

    k_wprep4<<<dim3(1024, 4), 1024>>>(
        (const float*)d_in[7], (const float*)d_in[8],
        (const float*)d_in[9], (const float*)d_in[10]);
    k_wprepT<<<dim3(512, 4, 2), dim3(32, 8)>>>(
        (const float*)d_in[11], (const float*)d_in[12]);
    k_mlp<<<dim3(12, 3), 256>>>(x, Wp, bp, Wh, bh, Wt, bt);
    k_prep<<<dim3(6, 4, 6), dim3(32, 8)>>>();
    k_stage1_all<<<dim3(128, 3, 6), 256, S1_SMEM>>>();
    k_stage23_all<<<dim3(2, 384, 6), 256, S23_SMEM>>>(out);
}